// round 4
// baseline (speedup 1.0000x reference)
#include <cuda_runtime.h>
#include <cstdint>
#include <math.h>

// ---------------- fixed problem shapes ----------------
#define N_TOK   32760
#define DIM     1536
#define NHEADS  12
#define HD      128
#define S_SP    1560
#define N_T     21
#define ENC     768
#define NA      32
#define KV_ROWS 672
#define LOG2_10000 13.287712379549449f

// ---------------- scratch ----------------
__device__ float g_xtf[N_TOK * DIM];
__device__ float g_q[N_TOK * DIM];
__device__ float g_attn[N_TOK * DIM];
__device__ float g_kv[KV_ROWS * 2 * DIM];
__device__ float g_k[KV_ROWS * DIM];
__device__ float g_v[KV_ROWS * DIM];
__device__ float g_qwtf[DIM * DIM];
__device__ float g_pwtf[DIM * DIM];
__device__ float g_pos[N_TOK];
__device__ float g_mm[4];

// ---------------- helpers ----------------
__device__ __forceinline__ uint32_t smem_u32(const void* p) {
    uint32_t r;
    asm("{.reg .u64 t; cvta.to.shared.u64 t, %1; cvt.u32.u64 %0, t;}" : "=r"(r) : "l"(p));
    return r;
}
__device__ __forceinline__ float tf32_rna(float x) {
    uint32_t u;
    asm("cvt.rna.tf32.f32 %0, %1;" : "=r"(u) : "f"(x));
    return __uint_as_float(u);
}

#define LDSM4(r0, r1, r2, r3, addr)                                            \
    asm volatile("ldmatrix.sync.aligned.m8n8.x4.shared.b16 {%0,%1,%2,%3}, [%4];" \
                 : "=r"(r0), "=r"(r1), "=r"(r2), "=r"(r3) : "r"(addr))

#define MMA_TF32(d, a, b0, b1)                                                 \
    asm volatile("mma.sync.aligned.m16n8k8.row.col.f32.tf32.tf32.f32 "          \
                 "{%0,%1,%2,%3},{%4,%5,%6,%7},{%8,%9},{%0,%1,%2,%3};"          \
                 : "+f"(d[0]), "+f"(d[1]), "+f"(d[2]), "+f"(d[3])              \
                 : "r"(a[0]), "r"(a[1]), "r"(a[2]), "r"(a[3]), "r"(b0), "r"(b1))

// ---------------- 0) tf32 RN rounding pass ----------------
__global__ void round_tf32_kernel(const float* __restrict__ in, float* __restrict__ out, int n4) {
    int i = blockIdx.x * blockDim.x + threadIdx.x;
    if (i >= n4) return;
    float4 v = ((const float4*)in)[i];
    v.x = tf32_rna(v.x); v.y = tf32_rna(v.y); v.z = tf32_rna(v.z); v.w = tf32_rna(v.w);
    ((float4*)out)[i] = v;
}

// ---------------- 1) min/max of attn-map rows ----------------
__global__ void minmax_kernel(const float* __restrict__ m) {
    __shared__ float s0[256], s1[256], s2[256], s3[256];
    int tid = threadIdx.x;
    float mn0 = 1e30f, mx0 = -1e30f, mn1 = 1e30f, mx1 = -1e30f;
    for (int i = tid; i < N_TOK; i += 256) {
        float v0 = m[i], v1 = m[N_TOK + i];
        mn0 = fminf(mn0, v0); mx0 = fmaxf(mx0, v0);
        mn1 = fminf(mn1, v1); mx1 = fmaxf(mx1, v1);
    }
    s0[tid] = mn0; s1[tid] = mx0; s2[tid] = mn1; s3[tid] = mx1;
    __syncthreads();
    for (int off = 128; off > 0; off >>= 1) {
        if (tid < off) {
            s0[tid] = fminf(s0[tid], s0[tid + off]);
            s1[tid] = fmaxf(s1[tid], s1[tid + off]);
            s2[tid] = fminf(s2[tid], s2[tid + off]);
            s3[tid] = fmaxf(s3[tid], s3[tid + off]);
        }
        __syncthreads();
    }
    if (tid == 0) { g_mm[0] = s0[0]; g_mm[1] = s1[0]; g_mm[2] = s2[0]; g_mm[3] = s3[0]; }
}

// ---------------- 2) routing positions ----------------
__global__ void pos_kernel(const float* __restrict__ m) {
    int n = blockIdx.x * blockDim.x + threadIdx.x;
    if (n >= N_TOK) return;
    float m0 = m[n], m1 = m[N_TOK + n];
    float r;
    if (m0 >= m1) r = (m0 - g_mm[0]) / (g_mm[1] - g_mm[0] + 1e-8f) * 4.0f;
    else          r = (m1 - g_mm[2]) / (g_mm[3] - g_mm[2] + 1e-8f) * 4.0f + 20.0f;
    g_pos[n] = r;
}

// ======== tf32 mma.sync GEMM: C[M,N] = A[M,K] @ B[N,K]^T + bias (+RoPE) ========
// CTA tile 128x256, 8 warps (2x4), warp tile 64x64, 4-stage cp.async pipeline.
#define KCHUNK  32
#define STAGES  4
#define SM_ASZ  16384                       // 128 x 32 x 4B
#define SM_BSZ  32768                       // 256 x 32 x 4B
#define SM_TOT  (STAGES * (SM_ASZ + SM_BSZ))  // 196608

__device__ __forceinline__ void fill_stage(
    const float* __restrict__ A, const float* __restrict__ B, int M, int K,
    int row0, int col0, int kt, uint32_t sA, uint32_t sB, int tid)
{
#pragma unroll
    for (int g = 0; g < 4; g++) {                // A: 128 rows x 8 chunks
        int ga = tid + g * 256;
        int row = ga >> 3, ch = ga & 7;
        uint32_t dst = sA + (uint32_t)row * 128u + (((uint32_t)ch * 16u) ^ (((uint32_t)row & 7u) << 4));
        const float* src = A + (size_t)(row0 + row) * K + kt * KCHUNK + ch * 4;
        int sz = (row0 + row < M) ? 16 : 0;
        asm volatile("cp.async.cg.shared.global [%0], [%1], 16, %2;" :: "r"(dst), "l"(src), "r"(sz));
    }
#pragma unroll
    for (int g = 0; g < 8; g++) {                // B: 256 rows x 8 chunks
        int gb = tid + g * 256;
        int row = gb >> 3, ch = gb & 7;
        uint32_t dst = sB + (uint32_t)row * 128u + (((uint32_t)ch * 16u) ^ (((uint32_t)row & 7u) << 4));
        const float* src = B + (size_t)(col0 + row) * K + kt * KCHUNK + ch * 4;
        asm volatile("cp.async.cg.shared.global [%0], [%1], 16;" :: "r"(dst), "l"(src));
    }
    asm volatile("cp.async.commit_group;");
}

template <bool FUSE_ROPE>
__global__ void __launch_bounds__(256, 1) gemm_tf32(
    const float* __restrict__ A, const float* __restrict__ B,
    const float* __restrict__ bias, float* __restrict__ C,
    int M, int N, int K)
{
    extern __shared__ float smem[];
    const int tid  = threadIdx.x;
    const int lane = tid & 31, warp = tid >> 5;
    const int wm = warp >> 2, wn = warp & 3;          // 2 x 4 warp grid, 64x64 tiles
    const int row0 = blockIdx.y * 128, col0 = blockIdx.x * 256;

    const uint32_t sA = smem_u32(smem);
    const uint32_t sB = sA + STAGES * SM_ASZ;
    const int ktiles = K / KCHUNK;

    fill_stage(A, B, M, K, row0, col0, 0, sA, sB, tid);
    fill_stage(A, B, M, K, row0, col0, 1, sA + SM_ASZ, sB + SM_BSZ, tid);
    fill_stage(A, B, M, K, row0, col0, 2, sA + 2 * SM_ASZ, sB + 2 * SM_BSZ, tid);

    float acc[4][8][4];
#pragma unroll
    for (int i = 0; i < 4; i++)
#pragma unroll
        for (int j = 0; j < 8; j++)
#pragma unroll
            for (int k = 0; k < 4; k++) acc[i][j][k] = 0.0f;

    const int aRow = wm * 64 + ((lane >> 3) & 1) * 8 + (lane & 7);
    const int bRow = wn * 64 + ((lane >> 3) & 1) * 8 + (lane & 7);
    const uint32_t colSel = ((lane >> 4) & 1) * 16;
    const uint32_t xorv = ((uint32_t)lane & 7u) << 4;

    for (int it = 0; it < ktiles; it++) {
        if (it < ktiles - 2)       asm volatile("cp.async.wait_group 2;" ::: "memory");
        else if (it == ktiles - 2) asm volatile("cp.async.wait_group 1;" ::: "memory");
        else                       asm volatile("cp.async.wait_group 0;" ::: "memory");
        __syncthreads();
        const int st = it & 3;
        const uint32_t bA = sA + st * SM_ASZ;
        const uint32_t bB = sB + st * SM_BSZ;
#pragma unroll
        for (int ks = 0; ks < 4; ks++) {
            uint32_t a[4][4], bb[4][4];
            const uint32_t cb = ((uint32_t)(ks * 32) + colSel) ^ xorv;
#pragma unroll
            for (int mf = 0; mf < 4; mf++) {
                uint32_t ad = bA + (uint32_t)(aRow + mf * 16) * 128 + cb;
                LDSM4(a[mf][0], a[mf][1], a[mf][2], a[mf][3], ad);
            }
#pragma unroll
            for (int nh = 0; nh < 4; nh++) {
                uint32_t bd = bB + (uint32_t)(bRow + nh * 16) * 128 + cb;
                LDSM4(bb[nh][0], bb[nh][1], bb[nh][2], bb[nh][3], bd);
            }
#pragma unroll
            for (int mf = 0; mf < 4; mf++)
#pragma unroll
                for (int nf = 0; nf < 8; nf++) {
                    const int nh = nf >> 1, lo = nf & 1;
                    MMA_TF32(acc[mf][nf], a[mf], bb[nh][lo], bb[nh][2 + lo]);
                }
        }
        if (it + 3 < ktiles) {
            const int r = it + 3;
            fill_stage(A, B, M, K, row0, col0, r,
                       sA + (r & 3) * SM_ASZ, sB + (r & 3) * SM_BSZ, tid);
        }
    }

    // epilogue: c0,c1 at (row=lane>>2, col=2*(lane&3)); c2,c3 at row+8
#pragma unroll
    for (int mf = 0; mf < 4; mf++) {
        const int r0 = row0 + wm * 64 + mf * 16 + (lane >> 2);
        const int r8 = r0 + 8;
        float pos0 = 0.f, pos8 = 0.f;
        if (FUSE_ROPE) {
            pos0 = g_pos[(r0 < M) ? r0 : 0];
            pos8 = g_pos[(r8 < M) ? r8 : 0];
        }
#pragma unroll
        for (int nf = 0; nf < 8; nf++) {
            const int c = col0 + wn * 64 + nf * 8 + (lane & 3) * 2;
            const float2 bv = *(const float2*)(bias + c);
            float o0 = acc[mf][nf][0] + bv.x;
            float o1 = acc[mf][nf][1] + bv.y;
            float o2 = acc[mf][nf][2] + bv.x;
            float o3 = acc[mf][nf][3] + bv.y;
            if (FUSE_ROPE) {
                const int i = (c & 127) >> 1;     // pair index within the 128-d head
                const float fr = exp2f(-(float)i * (LOG2_10000 / 64.0f));
                float sn, cs;
                sincosf(pos0 * fr, &sn, &cs);
                float t0 = o0 * cs - o1 * sn;
                o1 = o1 * cs + o0 * sn; o0 = t0;
                sincosf(pos8 * fr, &sn, &cs);
                float t2 = o2 * cs - o3 * sn;
                o3 = o3 * cs + o2 * sn; o2 = t2;
            }
            if (r0 < M) *(float2*)(C + (size_t)r0 * N + c) = make_float2(o0, o1);
            if (r8 < M) *(float2*)(C + (size_t)r8 * N + c) = make_float2(o2, o3);
        }
    }
}

// ---------------- fp32 SIMT GEMM (small kv projection) ----------
__global__ void __launch_bounds__(256) gemm_nt_bias(
    const float* __restrict__ A, const float* __restrict__ B,
    const float* __restrict__ bias, float* __restrict__ C,
    int M, int N, int K)
{
    __shared__ float As[8][128];
    __shared__ float Bs[8][128];
    const int tid  = threadIdx.x;
    const int row0 = blockIdx.y * 128;
    const int col0 = blockIdx.x * 128;
    const int tx = tid & 15, ty = tid >> 4;
    const int lr = tid >> 1, lc = (tid & 1) * 4;

    float acc[8][8];
#pragma unroll
    for (int i = 0; i < 8; i++)
#pragma unroll
        for (int j = 0; j < 8; j++) acc[i][j] = 0.0f;

    const bool arow_ok = (row0 + lr) < M;
    const float* Ap = A + (size_t)(row0 + lr) * K + lc;
    const float* Bp = B + (size_t)(col0 + lr) * K + lc;

    for (int k0 = 0; k0 < K; k0 += 8) {
        float4 av = arow_ok ? *(const float4*)(Ap + k0) : make_float4(0.f, 0.f, 0.f, 0.f);
        float4 bv = *(const float4*)(Bp + k0);
        As[lc + 0][lr] = av.x; As[lc + 1][lr] = av.y; As[lc + 2][lr] = av.z; As[lc + 3][lr] = av.w;
        Bs[lc + 0][lr] = bv.x; Bs[lc + 1][lr] = bv.y; Bs[lc + 2][lr] = bv.z; Bs[lc + 3][lr] = bv.w;
        __syncthreads();
#pragma unroll
        for (int k = 0; k < 8; k++) {
            float a[8], b[8];
#pragma unroll
            for (int i = 0; i < 8; i++) a[i] = As[k][ty * 8 + i];
#pragma unroll
            for (int j = 0; j < 8; j++) b[j] = Bs[k][tx * 8 + j];
#pragma unroll
            for (int i = 0; i < 8; i++)
#pragma unroll
                for (int j = 0; j < 8; j++)
                    acc[i][j] += a[i] * b[j];
        }
        __syncthreads();
    }
#pragma unroll
    for (int i = 0; i < 8; i++) {
        int r = row0 + ty * 8 + i;
        if (r < M) {
            float* Cp = C + (size_t)r * N + col0 + tx * 8;
            const float* bp = bias + col0 + tx * 8;
#pragma unroll
            for (int j = 0; j < 8; j++) Cp[j] = acc[i][j] + bp[j];
        }
    }
}

// ---------------- split kv -> k (bucket-centre RoPE) and v ----------------
__global__ void rope_k_split_kernel() {
    int idx = blockIdx.x * blockDim.x + threadIdx.x;
    if (idx >= KV_ROWS * (DIM / 2)) return;
    int r = idx / (DIM / 2);
    int p = idx - r * (DIM / 2);
    int a = r & 31;
    float pos = (a < 16) ? 2.0f : 22.0f;
    int i = p & 63;
    float fr = exp2f(-(float)i * (LOG2_10000 / 64.0f));
    float th = pos * fr;
    float s, c;
    sincosf(th, &s, &c);
    const float* kvr = g_kv + (size_t)r * (2 * DIM);
    float ka = kvr[2 * p], kb = kvr[2 * p + 1];
    size_t o = (size_t)r * DIM + 2 * p;
    g_k[o]     = ka * c - kb * s;
    g_k[o + 1] = kb * c + ka * s;
    g_v[o]     = kvr[DIM + 2 * p];
    g_v[o + 1] = kvr[DIM + 2 * p + 1];
}

// ---------------- cross-attention (KV len 32), tf32-rounded output -------
__global__ void __launch_bounds__(256) attn_kernel() {
    const int h = blockIdx.x;
    const int t = blockIdx.y;
    __shared__ float ks[32][132];
    __shared__ float vs[32][128];
    __shared__ float qs[8][128];

    const int tid = threadIdx.x;
    for (int i = tid; i < 32 * 128; i += 256) {
        int a = i >> 7, d = i & 127;
        size_t src = (size_t)(t * 32 + a) * DIM + h * HD + d;
        ks[a][d] = g_k[src];
        vs[a][d] = g_v[src];
    }
    __syncthreads();

    const int w = tid >> 5, l = tid & 31;
    const float4* vs4base = (const float4*)&vs[0][0];

    for (int s = w; s < S_SP; s += 8) {
        size_t rowoff = (size_t)(t * S_SP + s) * DIM + h * HD;
        ((float4*)&qs[w][0])[l] = ((const float4*)(g_q + rowoff))[l];
        __syncwarp();

        float acc = 0.0f;
        const float4* qr = (const float4*)&qs[w][0];
        const float4* kr = (const float4*)&ks[l][0];
#pragma unroll
        for (int j = 0; j < 32; j++) {
            float4 a4 = qr[j];
            float4 b4 = kr[j];
            acc += a4.x * b4.x + a4.y * b4.y + a4.z * b4.z + a4.w * b4.w;
        }
        acc *= 0.08838834764831845f;

        float mx = acc;
#pragma unroll
        for (int o = 16; o > 0; o >>= 1) mx = fmaxf(mx, __shfl_xor_sync(0xFFFFFFFFu, mx, o));
        float e = __expf(acc - mx);
        float sum = e;
#pragma unroll
        for (int o = 16; o > 0; o >>= 1) sum += __shfl_xor_sync(0xFFFFFFFFu, sum, o);
        float p = e / sum;

        float4 o4 = make_float4(0.f, 0.f, 0.f, 0.f);
#pragma unroll
        for (int a = 0; a < 32; a++) {
            float pa = __shfl_sync(0xFFFFFFFFu, p, a);
            float4 vv = vs4base[a * 32 + l];
            o4.x += pa * vv.x; o4.y += pa * vv.y; o4.z += pa * vv.z; o4.w += pa * vv.w;
        }
        o4.x = tf32_rna(o4.x); o4.y = tf32_rna(o4.y);
        o4.z = tf32_rna(o4.z); o4.w = tf32_rna(o4.w);
        ((float4*)(g_attn + rowoff))[l] = o4;
        __syncwarp();
    }
}

// ---------------- launch ----------------
extern "C" void kernel_launch(void* const* d_in, const int* in_sizes, int n_in,
                              void* d_out, int out_size)
{
    const float* x    = (const float*)d_in[0];
    const float* ehs  = (const float*)d_in[1];
    const float* amap = (const float*)d_in[2];
    const float* q_w  = (const float*)d_in[3];
    const float* q_b  = (const float*)d_in[4];
    const float* kv_w = (const float*)d_in[5];
    const float* kv_b = (const float*)d_in[6];
    const float* p_w  = (const float*)d_in[7];
    const float* p_b  = (const float*)d_in[8];
    float* out = (float*)d_out;

    float *xtf, *q, *attn, *kv, *qwtf, *pwtf;
    cudaGetSymbolAddress((void**)&xtf,  g_xtf);
    cudaGetSymbolAddress((void**)&q,    g_q);
    cudaGetSymbolAddress((void**)&attn, g_attn);
    cudaGetSymbolAddress((void**)&kv,   g_kv);
    cudaGetSymbolAddress((void**)&qwtf, g_qwtf);
    cudaGetSymbolAddress((void**)&pwtf, g_pwtf);

    cudaFuncSetAttribute(gemm_tf32<true>,  cudaFuncAttributeMaxDynamicSharedMemorySize, SM_TOT);
    cudaFuncSetAttribute(gemm_tf32<false>, cudaFuncAttributeMaxDynamicSharedMemorySize, SM_TOT);

    // routing positions
    minmax_kernel<<<1, 256>>>(amap);
    pos_kernel<<<(N_TOK + 255) / 256, 256>>>(amap);

    // tf32 RN pre-rounding of GEMM inputs
    {
        int n4x = (N_TOK * DIM) / 4;
        round_tf32_kernel<<<(n4x + 255) / 256, 256>>>(x, xtf, n4x);
        int n4w = (DIM * DIM) / 4;
        round_tf32_kernel<<<(n4w + 255) / 256, 256>>>(q_w, qwtf, n4w);
        round_tf32_kernel<<<(n4w + 255) / 256, 256>>>(p_w, pwtf, n4w);
    }

    // q = RoPE(x @ q_w^T + q_b)   (tf32 mma, fused RoPE epilogue)
    gemm_tf32<true><<<dim3(DIM / 256, (N_TOK + 127) / 128), 256, SM_TOT>>>(
        xtf, qwtf, q_b, q, N_TOK, DIM, DIM);

    // kv = ehs @ kv_w^T + kv_b  (fp32 SIMT keeps K/V exact)
    gemm_nt_bias<<<dim3((2 * DIM) / 128, (KV_ROWS + 127) / 128), 256>>>(
        ehs, kv_w, kv_b, kv, KV_ROWS, 2 * DIM, ENC);

    // split + RoPE(k)
    rope_k_split_kernel<<<(KV_ROWS * (DIM / 2) + 255) / 256, 256>>>();

    // cross-attention (rounds output to tf32)
    attn_kernel<<<dim3(NHEADS, N_T), 256>>>();

    // out = attn @ proj_w^T + proj_b
    gemm_tf32<false><<<dim3(DIM / 256, (N_TOK + 127) / 128), 256, SM_TOT>>>(
        attn, pwtf, p_b, out, N_TOK, DIM, DIM);
}

// round 5
// speedup vs baseline: 1.4570x; 1.4570x over previous
#include <cuda_runtime.h>
#include <cuda_fp16.h>
#include <cstdint>
#include <math.h>

// ---------------- fixed problem shapes ----------------
#define N_TOK   32760
#define DIM     1536
#define NHEADS  12
#define HD      128
#define S_SP    1560
#define N_T     21
#define ENC     768
#define NA      32
#define KV_ROWS 672
#define LOG2_10000 13.287712379549449f

// ---------------- scratch ----------------
__device__ __half g_xh[N_TOK * DIM];        // fp16 x
__device__ __half g_attnh[N_TOK * DIM];     // fp16 attention output
__device__ __half g_qwh[DIM * DIM];         // fp16 q_w
__device__ __half g_pwh[DIM * DIM];         // fp16 proj_w
__device__ float  g_q[N_TOK * DIM];         // RoPE'd q (fp32, read by attention)
__device__ float  g_kv[KV_ROWS * 2 * DIM];
__device__ float  g_k[KV_ROWS * DIM];
__device__ float  g_v[KV_ROWS * DIM];
__device__ float  g_pos[N_TOK];
__device__ float  g_mm[4];

// ---------------- helpers ----------------
__device__ __forceinline__ uint32_t smem_u32(const void* p) {
    uint32_t r;
    asm("{.reg .u64 t; cvta.to.shared.u64 t, %1; cvt.u32.u64 %0, t;}" : "=r"(r) : "l"(p));
    return r;
}

#define LDSM4(r0, r1, r2, r3, addr)                                            \
    asm volatile("ldmatrix.sync.aligned.m8n8.x4.shared.b16 {%0,%1,%2,%3}, [%4];" \
                 : "=r"(r0), "=r"(r1), "=r"(r2), "=r"(r3) : "r"(addr))

#define MMA_F16(d, a, b0, b1)                                                  \
    asm volatile("mma.sync.aligned.m16n8k16.row.col.f32.f16.f16.f32 "           \
                 "{%0,%1,%2,%3},{%4,%5,%6,%7},{%8,%9},{%0,%1,%2,%3};"          \
                 : "+f"(d[0]), "+f"(d[1]), "+f"(d[2]), "+f"(d[3])              \
                 : "r"(a[0]), "r"(a[1]), "r"(a[2]), "r"(a[3]), "r"(b0), "r"(b1))

// ---------------- 0) fp32 -> fp16 conversion ----------------
__global__ void cvt_half_kernel(const float* __restrict__ in, __half* __restrict__ out, int n4) {
    int i = blockIdx.x * blockDim.x + threadIdx.x;
    if (i >= n4) return;
    float4 v = ((const float4*)in)[i];
    __half2 h0 = __floats2half2_rn(v.x, v.y);
    __half2 h1 = __floats2half2_rn(v.z, v.w);
    uint2 pk;
    pk.x = *(uint32_t*)&h0;
    pk.y = *(uint32_t*)&h1;
    ((uint2*)out)[i] = pk;
}

// ---------------- 1) min/max of attn-map rows ----------------
__global__ void minmax_kernel(const float* __restrict__ m) {
    __shared__ float s0[256], s1[256], s2[256], s3[256];
    int tid = threadIdx.x;
    float mn0 = 1e30f, mx0 = -1e30f, mn1 = 1e30f, mx1 = -1e30f;
    for (int i = tid; i < N_TOK; i += 256) {
        float v0 = m[i], v1 = m[N_TOK + i];
        mn0 = fminf(mn0, v0); mx0 = fmaxf(mx0, v0);
        mn1 = fminf(mn1, v1); mx1 = fmaxf(mx1, v1);
    }
    s0[tid] = mn0; s1[tid] = mx0; s2[tid] = mn1; s3[tid] = mx1;
    __syncthreads();
    for (int off = 128; off > 0; off >>= 1) {
        if (tid < off) {
            s0[tid] = fminf(s0[tid], s0[tid + off]);
            s1[tid] = fmaxf(s1[tid], s1[tid + off]);
            s2[tid] = fminf(s2[tid], s2[tid + off]);
            s3[tid] = fmaxf(s3[tid], s3[tid + off]);
        }
        __syncthreads();
    }
    if (tid == 0) { g_mm[0] = s0[0]; g_mm[1] = s1[0]; g_mm[2] = s2[0]; g_mm[3] = s3[0]; }
}

// ---------------- 2) routing positions ----------------
__global__ void pos_kernel(const float* __restrict__ m) {
    int n = blockIdx.x * blockDim.x + threadIdx.x;
    if (n >= N_TOK) return;
    float m0 = m[n], m1 = m[N_TOK + n];
    float r;
    if (m0 >= m1) r = (m0 - g_mm[0]) / (g_mm[1] - g_mm[0] + 1e-8f) * 4.0f;
    else          r = (m1 - g_mm[2]) / (g_mm[3] - g_mm[2] + 1e-8f) * 4.0f + 20.0f;
    g_pos[n] = r;
}

// ======== fp16 mma.sync GEMM: C[M,N] = A[M,K] @ B[N,K]^T + bias (+RoPE) ========
// CTA tile 128x256, 8 warps (2x4), warp tile 64x64, mma.m16n8k16.f16,
// KCHUNK=64 halves (128B rows), 4-stage cp.async pipeline, fp32 epilogue.
#define KCHUNK  64
#define STAGES  4
#define SM_ASZ  16384                          // 128 rows x 128 B
#define SM_BSZ  32768                          // 256 rows x 128 B
#define SM_TOT  (STAGES * (SM_ASZ + SM_BSZ))   // 196608

__device__ __forceinline__ void fill_stage(
    const __half* __restrict__ A, const __half* __restrict__ B, int M, int K,
    int row0, int col0, int kt, uint32_t sA, uint32_t sB, int tid)
{
#pragma unroll
    for (int g = 0; g < 4; g++) {                // A: 128 rows x 8 chunks of 16B
        int ga = tid + g * 256;
        int row = ga >> 3, ch = ga & 7;
        uint32_t dst = sA + (uint32_t)row * 128u + (((uint32_t)ch * 16u) ^ (((uint32_t)row & 7u) << 4));
        const __half* src = A + (size_t)(row0 + row) * K + kt * KCHUNK + ch * 8;
        int sz = (row0 + row < M) ? 16 : 0;
        asm volatile("cp.async.cg.shared.global [%0], [%1], 16, %2;" :: "r"(dst), "l"(src), "r"(sz));
    }
#pragma unroll
    for (int g = 0; g < 8; g++) {                // B: 256 rows x 8 chunks of 16B
        int gb = tid + g * 256;
        int row = gb >> 3, ch = gb & 7;
        uint32_t dst = sB + (uint32_t)row * 128u + (((uint32_t)ch * 16u) ^ (((uint32_t)row & 7u) << 4));
        const __half* src = B + (size_t)(col0 + row) * K + kt * KCHUNK + ch * 8;
        asm volatile("cp.async.cg.shared.global [%0], [%1], 16;" :: "r"(dst), "l"(src));
    }
    asm volatile("cp.async.commit_group;");
}

template <bool FUSE_ROPE>
__global__ void __launch_bounds__(256, 1) gemm_f16(
    const __half* __restrict__ A, const __half* __restrict__ B,
    const float* __restrict__ bias, float* __restrict__ C,
    int M, int N, int K)
{
    extern __shared__ float smem[];
    const int tid  = threadIdx.x;
    const int lane = tid & 31, warp = tid >> 5;
    const int wm = warp >> 2, wn = warp & 3;          // 2 x 4 warp grid, 64x64 warp tiles
    const int row0 = blockIdx.y * 128, col0 = blockIdx.x * 256;

    const uint32_t sA = smem_u32(smem);
    const uint32_t sB = sA + STAGES * SM_ASZ;
    const int ktiles = K / KCHUNK;                    // 24

    fill_stage(A, B, M, K, row0, col0, 0, sA, sB, tid);
    fill_stage(A, B, M, K, row0, col0, 1, sA + SM_ASZ, sB + SM_BSZ, tid);
    fill_stage(A, B, M, K, row0, col0, 2, sA + 2 * SM_ASZ, sB + 2 * SM_BSZ, tid);

    float acc[4][8][4];
#pragma unroll
    for (int i = 0; i < 4; i++)
#pragma unroll
        for (int j = 0; j < 8; j++)
#pragma unroll
            for (int k = 0; k < 4; k++) acc[i][j][k] = 0.0f;

    // ldmatrix addressing: lanes 0-7 mat0 rows, 8-15 mat1(+8 rows), 16-23 mat2(k+8), 24-31 mat3
    const int aRow = wm * 64 + ((lane >> 3) & 1) * 8 + (lane & 7);
    const int bRow = wn * 64 + ((lane >> 3) & 1) * 8 + (lane & 7);
    const uint32_t colSel = ((lane >> 4) & 1) * 16;   // k8 half-step = 16 bytes
    const uint32_t xorv = ((uint32_t)lane & 7u) << 4;

    for (int it = 0; it < ktiles; it++) {
        if (it < ktiles - 2)       asm volatile("cp.async.wait_group 2;" ::: "memory");
        else if (it == ktiles - 2) asm volatile("cp.async.wait_group 1;" ::: "memory");
        else                       asm volatile("cp.async.wait_group 0;" ::: "memory");
        __syncthreads();
        const int st = it & 3;
        const uint32_t bA = sA + st * SM_ASZ;
        const uint32_t bB = sB + st * SM_BSZ;
#pragma unroll
        for (int ks = 0; ks < 4; ks++) {              // 4 x k16 per 64-half chunk
            uint32_t a[4][4], bb[4][4];
            const uint32_t cb = ((uint32_t)(ks * 32) + colSel) ^ xorv;  // k16 = 32 bytes
#pragma unroll
            for (int mf = 0; mf < 4; mf++) {
                uint32_t ad = bA + (uint32_t)(aRow + mf * 16) * 128 + cb;
                LDSM4(a[mf][0], a[mf][1], a[mf][2], a[mf][3], ad);
            }
#pragma unroll
            for (int ng = 0; ng < 4; ng++) {          // 4 x n16 groups
                uint32_t bd = bB + (uint32_t)(bRow + ng * 16) * 128 + cb;
                LDSM4(bb[ng][0], bb[ng][1], bb[ng][2], bb[ng][3], bd);
            }
#pragma unroll
            for (int mf = 0; mf < 4; mf++)
#pragma unroll
                for (int nf = 0; nf < 8; nf++) {
                    const int ng = nf >> 1, lo = nf & 1;
                    MMA_F16(acc[mf][nf], a[mf], bb[ng][lo], bb[ng][2 + lo]);
                }
        }
        if (it + 3 < ktiles) {
            const int r = it + 3;
            fill_stage(A, B, M, K, row0, col0, r,
                       sA + (r & 3) * SM_ASZ, sB + (r & 3) * SM_BSZ, tid);
        }
    }

    // epilogue: c0,c1 at (row=lane>>2, col=2*(lane&3)); c2,c3 at row+8
#pragma unroll
    for (int mf = 0; mf < 4; mf++) {
        const int r0 = row0 + wm * 64 + mf * 16 + (lane >> 2);
        const int r8 = r0 + 8;
        float pos0 = 0.f, pos8 = 0.f;
        if (FUSE_ROPE) {
            pos0 = g_pos[(r0 < M) ? r0 : 0];
            pos8 = g_pos[(r8 < M) ? r8 : 0];
        }
#pragma unroll
        for (int nf = 0; nf < 8; nf++) {
            const int c = col0 + wn * 64 + nf * 8 + (lane & 3) * 2;
            const float2 bv = *(const float2*)(bias + c);
            float o0 = acc[mf][nf][0] + bv.x;
            float o1 = acc[mf][nf][1] + bv.y;
            float o2 = acc[mf][nf][2] + bv.x;
            float o3 = acc[mf][nf][3] + bv.y;
            if (FUSE_ROPE) {
                const int i = (c & 127) >> 1;     // RoPE pair index within the 128-d head
                const float fr = exp2f(-(float)i * (LOG2_10000 / 64.0f));
                float sn, cs;
                sincosf(pos0 * fr, &sn, &cs);
                float t0 = o0 * cs - o1 * sn;
                o1 = o1 * cs + o0 * sn; o0 = t0;
                sincosf(pos8 * fr, &sn, &cs);
                float t2 = o2 * cs - o3 * sn;
                o3 = o3 * cs + o2 * sn; o2 = t2;
            }
            if (r0 < M) *(float2*)(C + (size_t)r0 * N + c) = make_float2(o0, o1);
            if (r8 < M) *(float2*)(C + (size_t)r8 * N + c) = make_float2(o2, o3);
        }
    }
}

// ---------------- fp32 SIMT GEMM (small kv projection; keeps K/V exact) ------
__global__ void __launch_bounds__(256) gemm_nt_bias(
    const float* __restrict__ A, const float* __restrict__ B,
    const float* __restrict__ bias, float* __restrict__ C,
    int M, int N, int K)
{
    __shared__ float As[8][128];
    __shared__ float Bs[8][128];
    const int tid  = threadIdx.x;
    const int row0 = blockIdx.y * 128;
    const int col0 = blockIdx.x * 128;
    const int tx = tid & 15, ty = tid >> 4;
    const int lr = tid >> 1, lc = (tid & 1) * 4;

    float acc[8][8];
#pragma unroll
    for (int i = 0; i < 8; i++)
#pragma unroll
        for (int j = 0; j < 8; j++) acc[i][j] = 0.0f;

    const bool arow_ok = (row0 + lr) < M;
    const float* Ap = A + (size_t)(row0 + lr) * K + lc;
    const float* Bp = B + (size_t)(col0 + lr) * K + lc;

    for (int k0 = 0; k0 < K; k0 += 8) {
        float4 av = arow_ok ? *(const float4*)(Ap + k0) : make_float4(0.f, 0.f, 0.f, 0.f);
        float4 bv = *(const float4*)(Bp + k0);
        As[lc + 0][lr] = av.x; As[lc + 1][lr] = av.y; As[lc + 2][lr] = av.z; As[lc + 3][lr] = av.w;
        Bs[lc + 0][lr] = bv.x; Bs[lc + 1][lr] = bv.y; Bs[lc + 2][lr] = bv.z; Bs[lc + 3][lr] = bv.w;
        __syncthreads();
#pragma unroll
        for (int k = 0; k < 8; k++) {
            float a[8], b[8];
#pragma unroll
            for (int i = 0; i < 8; i++) a[i] = As[k][ty * 8 + i];
#pragma unroll
            for (int j = 0; j < 8; j++) b[j] = Bs[k][tx * 8 + j];
#pragma unroll
            for (int i = 0; i < 8; i++)
#pragma unroll
                for (int j = 0; j < 8; j++)
                    acc[i][j] += a[i] * b[j];
        }
        __syncthreads();
    }
#pragma unroll
    for (int i = 0; i < 8; i++) {
        int r = row0 + ty * 8 + i;
        if (r < M) {
            float* Cp = C + (size_t)r * N + col0 + tx * 8;
            const float* bp = bias + col0 + tx * 8;
#pragma unroll
            for (int j = 0; j < 8; j++) Cp[j] = acc[i][j] + bp[j];
        }
    }
}

// ---------------- split kv -> k (bucket-centre RoPE) and v ----------------
__global__ void rope_k_split_kernel() {
    int idx = blockIdx.x * blockDim.x + threadIdx.x;
    if (idx >= KV_ROWS * (DIM / 2)) return;
    int r = idx / (DIM / 2);
    int p = idx - r * (DIM / 2);
    int a = r & 31;
    float pos = (a < 16) ? 2.0f : 22.0f;
    int i = p & 63;
    float fr = exp2f(-(float)i * (LOG2_10000 / 64.0f));
    float th = pos * fr;
    float s, c;
    sincosf(th, &s, &c);
    const float* kvr = g_kv + (size_t)r * (2 * DIM);
    float ka = kvr[2 * p], kb = kvr[2 * p + 1];
    size_t o = (size_t)r * DIM + 2 * p;
    g_k[o]     = ka * c - kb * s;
    g_k[o + 1] = kb * c + ka * s;
    g_v[o]     = kvr[DIM + 2 * p];
    g_v[o + 1] = kvr[DIM + 2 * p + 1];
}

// ---------------- cross-attention (KV len 32), fp16 output -------------------
__global__ void __launch_bounds__(256) attn_kernel() {
    const int h = blockIdx.x;
    const int t = blockIdx.y;
    __shared__ float ks[32][132];
    __shared__ float vs[32][128];
    __shared__ float qs[8][128];

    const int tid = threadIdx.x;
    for (int i = tid; i < 32 * 128; i += 256) {
        int a = i >> 7, d = i & 127;
        size_t src = (size_t)(t * 32 + a) * DIM + h * HD + d;
        ks[a][d] = g_k[src];
        vs[a][d] = g_v[src];
    }
    __syncthreads();

    const int w = tid >> 5, l = tid & 31;
    const float4* vs4base = (const float4*)&vs[0][0];

    for (int s = w; s < S_SP; s += 8) {
        size_t rowoff = (size_t)(t * S_SP + s) * DIM + h * HD;
        ((float4*)&qs[w][0])[l] = ((const float4*)(g_q + rowoff))[l];
        __syncwarp();

        float acc = 0.0f;
        const float4* qr = (const float4*)&qs[w][0];
        const float4* kr = (const float4*)&ks[l][0];
#pragma unroll
        for (int j = 0; j < 32; j++) {
            float4 a4 = qr[j];
            float4 b4 = kr[j];
            acc += a4.x * b4.x + a4.y * b4.y + a4.z * b4.z + a4.w * b4.w;
        }
        acc *= 0.08838834764831845f;

        float mx = acc;
#pragma unroll
        for (int o = 16; o > 0; o >>= 1) mx = fmaxf(mx, __shfl_xor_sync(0xFFFFFFFFu, mx, o));
        float e = __expf(acc - mx);
        float sum = e;
#pragma unroll
        for (int o = 16; o > 0; o >>= 1) sum += __shfl_xor_sync(0xFFFFFFFFu, sum, o);
        float p = e / sum;

        float4 o4 = make_float4(0.f, 0.f, 0.f, 0.f);
#pragma unroll
        for (int a = 0; a < 32; a++) {
            float pa = __shfl_sync(0xFFFFFFFFu, p, a);
            float4 vv = vs4base[a * 32 + l];
            o4.x += pa * vv.x; o4.y += pa * vv.y; o4.z += pa * vv.z; o4.w += pa * vv.w;
        }
        // emit fp16 directly for the proj GEMM
        __half2 h0 = __floats2half2_rn(o4.x, o4.y);
        __half2 h1 = __floats2half2_rn(o4.z, o4.w);
        uint2 pk;
        pk.x = *(uint32_t*)&h0;
        pk.y = *(uint32_t*)&h1;
        *(uint2*)(g_attnh + rowoff + 4 * l) = pk;
        __syncwarp();
    }
}

// ---------------- launch ----------------
extern "C" void kernel_launch(void* const* d_in, const int* in_sizes, int n_in,
                              void* d_out, int out_size)
{
    const float* x    = (const float*)d_in[0];
    const float* ehs  = (const float*)d_in[1];
    const float* amap = (const float*)d_in[2];
    const float* q_w  = (const float*)d_in[3];
    const float* q_b  = (const float*)d_in[4];
    const float* kv_w = (const float*)d_in[5];
    const float* kv_b = (const float*)d_in[6];
    const float* p_w  = (const float*)d_in[7];
    const float* p_b  = (const float*)d_in[8];
    float* out = (float*)d_out;

    __half *xh, *attnh, *qwh, *pwh;
    float *q, *kv;
    cudaGetSymbolAddress((void**)&xh,    g_xh);
    cudaGetSymbolAddress((void**)&attnh, g_attnh);
    cudaGetSymbolAddress((void**)&qwh,   g_qwh);
    cudaGetSymbolAddress((void**)&pwh,   g_pwh);
    cudaGetSymbolAddress((void**)&q,     g_q);
    cudaGetSymbolAddress((void**)&kv,    g_kv);

    cudaFuncSetAttribute(gemm_f16<true>,  cudaFuncAttributeMaxDynamicSharedMemorySize, SM_TOT);
    cudaFuncSetAttribute(gemm_f16<false>, cudaFuncAttributeMaxDynamicSharedMemorySize, SM_TOT);

    // routing positions
    minmax_kernel<<<1, 256>>>(amap);
    pos_kernel<<<(N_TOK + 255) / 256, 256>>>(amap);

    // fp16 conversion of GEMM inputs
    {
        int n4x = (N_TOK * DIM) / 4;
        cvt_half_kernel<<<(n4x + 255) / 256, 256>>>(x, xh, n4x);
        int n4w = (DIM * DIM) / 4;
        cvt_half_kernel<<<(n4w + 255) / 256, 256>>>(q_w, qwh, n4w);
        cvt_half_kernel<<<(n4w + 255) / 256, 256>>>(p_w, pwh, n4w);
    }

    // q = RoPE(x @ q_w^T + q_b)   (fp16 mma, fp32 accumulate, fused RoPE epilogue)
    gemm_f16<true><<<dim3(DIM / 256, (N_TOK + 127) / 128), 256, SM_TOT>>>(
        xh, qwh, q_b, q, N_TOK, DIM, DIM);

    // kv = ehs @ kv_w^T + kv_b  (fp32 SIMT keeps K/V exact)
    gemm_nt_bias<<<dim3((2 * DIM) / 128, (KV_ROWS + 127) / 128), 256>>>(
        ehs, kv_w, kv_b, kv, KV_ROWS, 2 * DIM, ENC);

    // split + RoPE(k)
    rope_k_split_kernel<<<(KV_ROWS * (DIM / 2) + 255) / 256, 256>>>();

    // cross-attention (emits fp16)
    attn_kernel<<<dim3(NHEADS, N_T), 256>>>();

    // out = attn @ proj_w^T + proj_b
    gemm_f16<false><<<dim3(DIM / 256, (N_TOK + 127) / 128), 256, SM_TOT>>>(
        attnh, pwh, p_b, out, N_TOK, DIM, DIM);
}

// round 7
// speedup vs baseline: 2.0143x; 1.3824x over previous
#include <cuda_runtime.h>
#include <cuda_fp16.h>
#include <cstdint>
#include <math.h>

// ---------------- fixed problem shapes ----------------
#define N_TOK   32760          // 21 * 1560
#define DIM     1536
#define NHEADS  12
#define HD      128
#define S_SP    1560
#define N_T     21
#define ENC     768
#define NA      32
#define KV_ROWS 672
#define PKDIM   384            // NHEADS * NA
#define LOG2_10000 13.287712379549449f

// ---------------- scratch ----------------
__device__ __half g_xh[N_TOK * DIM];          // fp16 x
__device__ __half g_qh[N_TOK * DIM];          // fp16 RoPE'd q
__device__ __half g_qwh[DIM * DIM];           // fp16 q_w
__device__ __half g_ehsh[KV_ROWS * ENC];      // fp16 encoder states
__device__ __half g_kvwh[2 * DIM * ENC];      // fp16 kv_w
__device__ float  g_kv[KV_ROWS * 2 * DIM];    // kv projection (fp32)
__device__ float  g_k[KV_ROWS * DIM];
__device__ float  g_v[KV_ROWS * DIM];
__device__ __half g_probsh[N_TOK * PKDIM];    // softmax probs [t*S+s][h*32+a]
__device__ __half g_w2h[N_T * DIM * PKDIM];   // W2^T [b][c][h*32+a]
__device__ float  g_pos[N_TOK];
__device__ float  g_mm[4];

// ---------------- helpers ----------------
__device__ __forceinline__ uint32_t smem_u32(const void* p) {
    uint32_t r;
    asm("{.reg .u64 t; cvta.to.shared.u64 t, %1; cvt.u32.u64 %0, t;}" : "=r"(r) : "l"(p));
    return r;
}

#define LDSM4(r0, r1, r2, r3, addr)                                            \
    asm volatile("ldmatrix.sync.aligned.m8n8.x4.shared.b16 {%0,%1,%2,%3}, [%4];" \
                 : "=r"(r0), "=r"(r1), "=r"(r2), "=r"(r3) : "r"(addr))

#define MMA_F16(d, a, b0, b1)                                                  \
    asm volatile("mma.sync.aligned.m16n8k16.row.col.f32.f16.f16.f32 "           \
                 "{%0,%1,%2,%3},{%4,%5,%6,%7},{%8,%9},{%0,%1,%2,%3};"          \
                 : "+f"(d[0]), "+f"(d[1]), "+f"(d[2]), "+f"(d[3])              \
                 : "r"(a[0]), "r"(a[1]), "r"(a[2]), "r"(a[3]), "r"(b0), "r"(b1))

// ---------------- fp32 -> fp16 conversion ----------------
__global__ void cvt_half_kernel(const float* __restrict__ in, __half* __restrict__ out, int n4) {
    int i = blockIdx.x * blockDim.x + threadIdx.x;
    if (i >= n4) return;
    float4 v = ((const float4*)in)[i];
    __half2 h0 = __floats2half2_rn(v.x, v.y);
    __half2 h1 = __floats2half2_rn(v.z, v.w);
    uint2 pk;
    pk.x = *(uint32_t*)&h0;
    pk.y = *(uint32_t*)&h1;
    ((uint2*)out)[i] = pk;
}

// ---------------- min/max of attn-map rows ----------------
__global__ void minmax_kernel(const float* __restrict__ m) {
    __shared__ float s0[256], s1[256], s2[256], s3[256];
    int tid = threadIdx.x;
    float mn0 = 1e30f, mx0 = -1e30f, mn1 = 1e30f, mx1 = -1e30f;
    for (int i = tid; i < N_TOK; i += 256) {
        float v0 = m[i], v1 = m[N_TOK + i];
        mn0 = fminf(mn0, v0); mx0 = fmaxf(mx0, v0);
        mn1 = fminf(mn1, v1); mx1 = fmaxf(mx1, v1);
    }
    s0[tid] = mn0; s1[tid] = mx0; s2[tid] = mn1; s3[tid] = mx1;
    __syncthreads();
    for (int off = 128; off > 0; off >>= 1) {
        if (tid < off) {
            s0[tid] = fminf(s0[tid], s0[tid + off]);
            s1[tid] = fmaxf(s1[tid], s1[tid + off]);
            s2[tid] = fminf(s2[tid], s2[tid + off]);
            s3[tid] = fmaxf(s3[tid], s3[tid + off]);
        }
        __syncthreads();
    }
    if (tid == 0) { g_mm[0] = s0[0]; g_mm[1] = s1[0]; g_mm[2] = s2[0]; g_mm[3] = s3[0]; }
}

// ---------------- routing positions ----------------
__global__ void pos_kernel(const float* __restrict__ m) {
    int n = blockIdx.x * blockDim.x + threadIdx.x;
    if (n >= N_TOK) return;
    float m0 = m[n], m1 = m[N_TOK + n];
    float r;
    if (m0 >= m1) r = (m0 - g_mm[0]) / (g_mm[1] - g_mm[0] + 1e-8f) * 4.0f;
    else          r = (m1 - g_mm[2]) / (g_mm[3] - g_mm[2] + 1e-8f) * 4.0f + 20.0f;
    g_pos[n] = r;
}

// ======== fp16 mma GEMM: C[M,N] = A[M,K] @ B[N,K]^T + bias (+RoPE, batched) ========
#define KCHUNK  64
#define STAGES  4
#define SM_ASZ  16384
#define SM_BSZ  32768
#define SM_TOT  (STAGES * (SM_ASZ + SM_BSZ))   // 196608

__device__ __forceinline__ void fill_stage(
    const __half* __restrict__ A, const __half* __restrict__ B, int M, int K,
    int row0, int col0, int kt, uint32_t sA, uint32_t sB, int tid)
{
#pragma unroll
    for (int g = 0; g < 4; g++) {                // A: 128 rows x 8 chunks of 16B
        int ga = tid + g * 256;
        int row = ga >> 3, ch = ga & 7;
        uint32_t dst = sA + (uint32_t)row * 128u + (((uint32_t)ch * 16u) ^ (((uint32_t)row & 7u) << 4));
        const __half* src = A + (size_t)(row0 + row) * K + kt * KCHUNK + ch * 8;
        int sz = (row0 + row < M) ? 16 : 0;
        asm volatile("cp.async.cg.shared.global [%0], [%1], 16, %2;" :: "r"(dst), "l"(src), "r"(sz));
    }
#pragma unroll
    for (int g = 0; g < 8; g++) {                // B: 256 rows x 8 chunks of 16B
        int gb = tid + g * 256;
        int row = gb >> 3, ch = gb & 7;
        uint32_t dst = sB + (uint32_t)row * 128u + (((uint32_t)ch * 16u) ^ (((uint32_t)row & 7u) << 4));
        const __half* src = B + (size_t)(col0 + row) * K + kt * KCHUNK + ch * 8;
        asm volatile("cp.async.cg.shared.global [%0], [%1], 16;" :: "r"(dst), "l"(src));
    }
    asm volatile("cp.async.commit_group;");
}

template <bool FUSE_ROPE, bool HALF_OUT>
__global__ void __launch_bounds__(256, 1) gemm_f16(
    const __half* __restrict__ A, const __half* __restrict__ B,
    const float* __restrict__ bias, void* __restrict__ Cv,
    int M, int N, int K, size_t strA, size_t strB, size_t strC)
{
    extern __shared__ float smem[];
    const int tid  = threadIdx.x;
    const int lane = tid & 31, warp = tid >> 5;
    const int wm = warp >> 2, wn = warp & 3;
    const int row0 = blockIdx.y * 128, col0 = blockIdx.x * 256;

    A += (size_t)blockIdx.z * strA;
    B += (size_t)blockIdx.z * strB;

    const uint32_t sA = smem_u32(smem);
    const uint32_t sB = sA + STAGES * SM_ASZ;
    const int ktiles = K / KCHUNK;

    fill_stage(A, B, M, K, row0, col0, 0, sA, sB, tid);
    fill_stage(A, B, M, K, row0, col0, 1, sA + SM_ASZ, sB + SM_BSZ, tid);
    fill_stage(A, B, M, K, row0, col0, 2, sA + 2 * SM_ASZ, sB + 2 * SM_BSZ, tid);

    float acc[4][8][4];
#pragma unroll
    for (int i = 0; i < 4; i++)
#pragma unroll
        for (int j = 0; j < 8; j++)
#pragma unroll
            for (int k = 0; k < 4; k++) acc[i][j][k] = 0.0f;

    const int aRow = wm * 64 + ((lane >> 3) & 1) * 8 + (lane & 7);
    const int bRow = wn * 64 + ((lane >> 3) & 1) * 8 + (lane & 7);
    const uint32_t colSel = ((lane >> 4) & 1) * 16;
    const uint32_t xorv = ((uint32_t)lane & 7u) << 4;

    for (int it = 0; it < ktiles; it++) {
        if (it < ktiles - 2)       asm volatile("cp.async.wait_group 2;" ::: "memory");
        else if (it == ktiles - 2) asm volatile("cp.async.wait_group 1;" ::: "memory");
        else                       asm volatile("cp.async.wait_group 0;" ::: "memory");
        __syncthreads();
        const int st = it & 3;
        const uint32_t bA = sA + st * SM_ASZ;
        const uint32_t bB = sB + st * SM_BSZ;
#pragma unroll
        for (int ks = 0; ks < 4; ks++) {
            uint32_t a[4][4], bb[4][4];
            const uint32_t cb = ((uint32_t)(ks * 32) + colSel) ^ xorv;
#pragma unroll
            for (int mf = 0; mf < 4; mf++) {
                uint32_t ad = bA + (uint32_t)(aRow + mf * 16) * 128 + cb;
                LDSM4(a[mf][0], a[mf][1], a[mf][2], a[mf][3], ad);
            }
#pragma unroll
            for (int ng = 0; ng < 4; ng++) {
                uint32_t bd = bB + (uint32_t)(bRow + ng * 16) * 128 + cb;
                LDSM4(bb[ng][0], bb[ng][1], bb[ng][2], bb[ng][3], bd);
            }
#pragma unroll
            for (int mf = 0; mf < 4; mf++)
#pragma unroll
                for (int nf = 0; nf < 8; nf++) {
                    const int ng = nf >> 1, lo = nf & 1;
                    MMA_F16(acc[mf][nf], a[mf], bb[ng][lo], bb[ng][2 + lo]);
                }
        }
        if (it + 3 < ktiles) {
            const int r = it + 3;
            fill_stage(A, B, M, K, row0, col0, r,
                       sA + (r & 3) * SM_ASZ, sB + (r & 3) * SM_BSZ, tid);
        }
    }

    // epilogue: c0,c1 at (row=lane>>2, col=2*(lane&3)); c2,c3 at row+8
#pragma unroll
    for (int mf = 0; mf < 4; mf++) {
        const int r0 = row0 + wm * 64 + mf * 16 + (lane >> 2);
        const int r8 = r0 + 8;
        float pos0 = 0.f, pos8 = 0.f;
        if (FUSE_ROPE) {
            pos0 = g_pos[(r0 < M) ? r0 : 0];
            pos8 = g_pos[(r8 < M) ? r8 : 0];
        }
#pragma unroll
        for (int nf = 0; nf < 8; nf++) {
            const int c = col0 + wn * 64 + nf * 8 + (lane & 3) * 2;
            const float2 bv = *(const float2*)(bias + c);
            float o0 = acc[mf][nf][0] + bv.x;
            float o1 = acc[mf][nf][1] + bv.y;
            float o2 = acc[mf][nf][2] + bv.x;
            float o3 = acc[mf][nf][3] + bv.y;
            if (FUSE_ROPE) {
                const int i = (c & 127) >> 1;
                const float fr = exp2f(-(float)i * (LOG2_10000 / 64.0f));
                float sn, cs;
                sincosf(pos0 * fr, &sn, &cs);
                float t0 = o0 * cs - o1 * sn;
                o1 = o1 * cs + o0 * sn; o0 = t0;
                sincosf(pos8 * fr, &sn, &cs);
                float t2 = o2 * cs - o3 * sn;
                o3 = o3 * cs + o2 * sn; o2 = t2;
            }
            if (HALF_OUT) {
                __half* C = (__half*)Cv + (size_t)blockIdx.z * strC;
                if (r0 < M) *(__half2*)(C + (size_t)r0 * N + c) = __floats2half2_rn(o0, o1);
                if (r8 < M) *(__half2*)(C + (size_t)r8 * N + c) = __floats2half2_rn(o2, o3);
            } else {
                float* C = (float*)Cv + (size_t)blockIdx.z * strC;
                if (r0 < M) *(float2*)(C + (size_t)r0 * N + c) = make_float2(o0, o1);
                if (r8 < M) *(float2*)(C + (size_t)r8 * N + c) = make_float2(o2, o3);
            }
        }
    }
}

// ---------------- split kv -> k (bucket-centre RoPE) and v ----------------
__global__ void rope_k_split_kernel() {
    int idx = blockIdx.x * blockDim.x + threadIdx.x;
    if (idx >= KV_ROWS * (DIM / 2)) return;
    int r = idx / (DIM / 2);
    int p = idx - r * (DIM / 2);
    int a = r & 31;
    float pos = (a < 16) ? 2.0f : 22.0f;
    int i = p & 63;
    float fr = exp2f(-(float)i * (LOG2_10000 / 64.0f));
    float th = pos * fr;
    float s, c;
    sincosf(th, &s, &c);
    const float* kvr = g_kv + (size_t)r * (2 * DIM);
    float ka = kvr[2 * p], kb = kvr[2 * p + 1];
    size_t o = (size_t)r * DIM + 2 * p;
    g_k[o]     = ka * c - kb * s;
    g_k[o + 1] = kb * c + ka * s;
    g_v[o]     = kvr[DIM + 2 * p];
    g_v[o + 1] = kvr[DIM + 2 * p + 1];
}

// ---------------- attention probs: scores + softmax only (KV len 32) ----------
__global__ void __launch_bounds__(256) attn_probs_kernel() {
    const int h = blockIdx.x;
    const int t = blockIdx.y;
    __shared__ float ks[32][129];      // stride 129: conflict-free per-lane row reads
    __shared__ __half qs[8][128];

    const int tid = threadIdx.x;
    for (int i = tid; i < 32 * 128; i += 256) {
        int a = i >> 7, d = i & 127;
        ks[a][d] = g_k[(size_t)(t * 32 + a) * DIM + h * HD + d];
    }
    __syncthreads();

    const int w = tid >> 5, l = tid & 31;

    for (int s = w; s < S_SP; s += 8) {
        size_t qoff = (size_t)(t * S_SP + s) * DIM + h * HD;
        ((uint2*)&qs[w][0])[l] = *(const uint2*)(g_qh + qoff + 4 * l);
        __syncwarp();

        float acc = 0.0f;
        const __half2* q2 = (const __half2*)&qs[w][0];
        const float* kr = &ks[l][0];
#pragma unroll
        for (int j = 0; j < 64; j++) {
            float2 qf = __half22float2(q2[j]);
            acc += qf.x * kr[2 * j] + qf.y * kr[2 * j + 1];
        }
        acc *= 0.08838834764831845f;

        float mx = acc;
#pragma unroll
        for (int o = 16; o > 0; o >>= 1) mx = fmaxf(mx, __shfl_xor_sync(0xFFFFFFFFu, mx, o));
        float e = __expf(acc - mx);
        float sum = e;
#pragma unroll
        for (int o = 16; o > 0; o >>= 1) sum += __shfl_xor_sync(0xFFFFFFFFu, sum, o);
        float p = e / sum;

        g_probsh[(size_t)(t * S_SP + s) * PKDIM + h * NA + l] = __float2half_rn(p);
        __syncwarp();
    }
}

// ---------------- W2[b,h] = V[b,h] @ proj_slice_h  (rank-32 fold of proj) -----
// output layout: g_w2h[b][c][h*32+a]  (B-operand [N=1536, K=384] for final GEMM)
__global__ void __launch_bounds__(128) w2_kernel(const float* __restrict__ pw) {
    const int ct = blockIdx.x;     // 0..11  (c tile of 128)
    const int h  = blockIdx.y;     // 0..11
    const int b  = blockIdx.z;     // 0..20
    __shared__ float Vs[32][128];

    const int tid = threadIdx.x;
    for (int i = tid; i < 32 * 128; i += 128) {
        int a = i >> 7, d = i & 127;
        Vs[a][d] = g_v[(size_t)(b * 32 + a) * DIM + h * HD + d];
    }
    __syncthreads();

    const int c = ct * 128 + tid;
    float acc[32];
#pragma unroll
    for (int a = 0; a < 32; a++) acc[a] = 0.0f;

    const float* pwr = pw + (size_t)c * DIM + h * HD;
#pragma unroll
    for (int chunk = 0; chunk < 4; chunk++) {
        float pr[32];
#pragma unroll
        for (int j = 0; j < 8; j++) {
            float4 v4 = *(const float4*)(pwr + chunk * 32 + j * 4);
            pr[j * 4 + 0] = v4.x; pr[j * 4 + 1] = v4.y;
            pr[j * 4 + 2] = v4.z; pr[j * 4 + 3] = v4.w;
        }
#pragma unroll
        for (int a = 0; a < 32; a++) {
#pragma unroll
            for (int j = 0; j < 32; j++)
                acc[a] += pr[j] * Vs[a][chunk * 32 + j];
        }
    }

    __half* dst = g_w2h + (size_t)b * DIM * PKDIM + (size_t)c * PKDIM + h * NA;
#pragma unroll
    for (int a = 0; a < 32; a += 2)
        *(__half2*)(dst + a) = __floats2half2_rn(acc[a], acc[a + 1]);
}

// ---------------- launch ----------------
extern "C" void kernel_launch(void* const* d_in, const int* in_sizes, int n_in,
                              void* d_out, int out_size)
{
    const float* x    = (const float*)d_in[0];
    const float* ehs  = (const float*)d_in[1];
    const float* amap = (const float*)d_in[2];
    const float* q_w  = (const float*)d_in[3];
    const float* q_b  = (const float*)d_in[4];
    const float* kv_w = (const float*)d_in[5];
    const float* kv_b = (const float*)d_in[6];
    const float* p_w  = (const float*)d_in[7];
    const float* p_b  = (const float*)d_in[8];
    float* out = (float*)d_out;

    __half *xh, *qh, *qwh, *ehsh, *kvwh, *probsh, *w2h;
    float *kv;
    cudaGetSymbolAddress((void**)&xh,     g_xh);
    cudaGetSymbolAddress((void**)&qh,     g_qh);
    cudaGetSymbolAddress((void**)&qwh,    g_qwh);
    cudaGetSymbolAddress((void**)&ehsh,   g_ehsh);
    cudaGetSymbolAddress((void**)&kvwh,   g_kvwh);
    cudaGetSymbolAddress((void**)&probsh, g_probsh);
    cudaGetSymbolAddress((void**)&w2h,    g_w2h);
    cudaGetSymbolAddress((void**)&kv,     g_kv);

    cudaFuncSetAttribute((const void*)gemm_f16<true, true>,
                         cudaFuncAttributeMaxDynamicSharedMemorySize, SM_TOT);
    cudaFuncSetAttribute((const void*)gemm_f16<false, false>,
                         cudaFuncAttributeMaxDynamicSharedMemorySize, SM_TOT);

    // routing positions
    minmax_kernel<<<1, 256>>>(amap);
    pos_kernel<<<(N_TOK + 255) / 256, 256>>>(amap);

    // fp16 conversions
    cvt_half_kernel<<<(N_TOK * DIM / 4 + 255) / 256, 256>>>(x, xh, N_TOK * DIM / 4);
    cvt_half_kernel<<<(DIM * DIM / 4 + 255) / 256, 256>>>(q_w, qwh, DIM * DIM / 4);
    cvt_half_kernel<<<(KV_ROWS * ENC / 4 + 255) / 256, 256>>>(ehs, ehsh, KV_ROWS * ENC / 4);
    cvt_half_kernel<<<(2 * DIM * ENC / 4 + 255) / 256, 256>>>(kv_w, kvwh, 2 * DIM * ENC / 4);

    // q = RoPE(x @ q_w^T + q_b) -> fp16
    gemm_f16<true, true><<<dim3(DIM / 256, (N_TOK + 127) / 128, 1), 256, SM_TOT>>>(
        xh, qwh, q_b, qh, N_TOK, DIM, DIM, 0, 0, 0);

    // kv = ehs @ kv_w^T + kv_b -> fp32
    gemm_f16<false, false><<<dim3((2 * DIM) / 256, (KV_ROWS + 127) / 128, 1), 256, SM_TOT>>>(
        ehsh, kvwh, kv_b, kv, KV_ROWS, 2 * DIM, ENC, 0, 0, 0);

    // split + RoPE(k)
    rope_k_split_kernel<<<(KV_ROWS * (DIM / 2) + 255) / 256, 256>>>();

    // attention probabilities
    attn_probs_kernel<<<dim3(NHEADS, N_T), 256>>>();

    // W2 = V @ proj (per frame, per head) -> fp16 [b][c][h*32+a]
    w2_kernel<<<dim3(DIM / 128, NHEADS, N_T), 128>>>(p_w);

    // out[b] = probs[b] @ W2[b]^T + p_b   (batched over 21 frames, K=384)
    gemm_f16<false, false><<<dim3(DIM / 256, (S_SP + 127) / 128, N_T), 256, SM_TOT>>>(
        probsh, w2h, p_b, out, S_SP, DIM, PKDIM,
        (size_t)S_SP * PKDIM, (size_t)DIM * PKDIM, (size_t)S_SP * DIM);
}